// round 15
// baseline (speedup 1.0000x reference)
#include <cuda_runtime.h>
#include <cuda_bf16.h>
#include <cuda_fp16.h>
#include <cstdint>

// Problem constants
#define NN   50000
#define NPAD 50048
#define EE   1600000
#define RR   16
#define NB   4
#define HH   128
#define GG   64
#define NC   2

#define KTOT 640
#define MTILE 64
#define NTILE 128
#define KCHUNK 64
#define NCHUNKS 10
#define GEMM_GRID ((NN + MTILE - 1) / MTILE)   // 782
// stage: Ah(8K) Al(8K) Bh(16K) Bl(16K) = 48KB
#define A_LO_OFF 8192
#define B_HI_OFF 16384
#define B_LO_OFF 32768
#define STAGE_BYTES 49152
#define GEMM_SMEM (2 * STAGE_BYTES)            // 96KB -> 2 CTAs/SM

#define SCAN_B 256
#define SCAN_G ((NN + SCAN_B - 1) / SCAN_B)    // 196

// ---------------- device scratch (static, no allocs) ----------------
__device__ unsigned int d_csr[EE];
__device__ int   d_rowptr[NN + 1];
__device__ int   d_deg[NN];
__device__ int   d_typeoff[NN * RR];
__device__ int   d_cnt[NN * RR];
__device__ float d_invcnt[NN * RR];
__device__ int   d_part[SCAN_G];
__device__ int   d_partpre[SCAN_G];
__device__ float d_pool[GG * HH];
__device__ float d_poolcnt[GG];
// fp16 gather mirrors
__device__ __half d_x16[(size_t)NPAD * HH];
__device__ __half d_h1_16[(size_t)NPAD * HH];
__device__ __half d_h2_16[(size_t)NPAD * HH];
// pre-split bf16 operands (padded rows)
__device__ __nv_bfloat16 d_z_hi[(size_t)NPAD * 512];
__device__ __nv_bfloat16 d_z_lo[(size_t)NPAD * 512];
__device__ __nv_bfloat16 d_x_hi[(size_t)NPAD * HH];
__device__ __nv_bfloat16 d_x_lo[(size_t)NPAD * HH];
__device__ __nv_bfloat16 d_h1_hi[(size_t)NPAD * HH];
__device__ __nv_bfloat16 d_h1_lo[(size_t)NPAD * HH];
__device__ __nv_bfloat16 d_h2_hi[(size_t)NPAD * HH];
__device__ __nv_bfloat16 d_h2_lo[(size_t)NPAD * HH];
// transposed + hi/lo split weights: [layer][n(128)][k(640)]
__device__ __nv_bfloat16 d_wt_hi[3 * NTILE * KTOT];
__device__ __nv_bfloat16 d_wt_lo[3 * NTILE * KTOT];

// ---------------- helpers ----------------
__device__ __forceinline__ uint32_t smem_u32(const void* p) {
    uint32_t a;
    asm("{ .reg .u64 t; cvta.to.shared.u64 t, %1; cvt.u32.u64 %0, t; }" : "=r"(a) : "l"(p));
    return a;
}
#define SW128(o) ((o) ^ (((o) >> 3) & 0x70))

__device__ __forceinline__ void split2(float a, float b, uint32_t& hi, uint32_t& lo) {
    __nv_bfloat16 ha = __float2bfloat16(a), hb = __float2bfloat16(b);
    float fa = __bfloat162float(ha), fb = __bfloat162float(hb);
    __nv_bfloat16 la = __float2bfloat16(a - fa), lb = __float2bfloat16(b - fb);
    hi = (uint32_t)__bfloat16_as_ushort(ha) | ((uint32_t)__bfloat16_as_ushort(hb) << 16);
    lo = (uint32_t)__bfloat16_as_ushort(la) | ((uint32_t)__bfloat16_as_ushort(lb) << 16);
}

__device__ __forceinline__ void ldsm_x4(uint32_t* r, uint32_t addr) {
    asm volatile("ldmatrix.sync.aligned.m8n8.x4.shared.b16 {%0,%1,%2,%3}, [%4];"
                 : "=r"(r[0]), "=r"(r[1]), "=r"(r[2]), "=r"(r[3]) : "r"(addr));
}
__device__ __forceinline__ void mma_bf16(float* d, const uint32_t* a, uint32_t b0, uint32_t b1) {
    asm volatile(
        "mma.sync.aligned.m16n8k16.row.col.f32.bf16.bf16.f32 "
        "{%0,%1,%2,%3}, {%4,%5,%6,%7}, {%8,%9}, {%0,%1,%2,%3};"
        : "+f"(d[0]), "+f"(d[1]), "+f"(d[2]), "+f"(d[3])
        : "r"(a[0]), "r"(a[1]), "r"(a[2]), "r"(a[3]), "r"(b0), "r"(b1));
}
__device__ __forceinline__ void cp16(uint32_t smem_dst, const void* gsrc) {
    asm volatile("cp.async.cg.shared.global [%0], [%1], 16;" :: "r"(smem_dst), "l"(gsrc));
}
__device__ __forceinline__ void cp_commit() {
    asm volatile("cp.async.commit_group;" ::: "memory");
}
template<int N> __device__ __forceinline__ void cp_wait() {
    asm volatile("cp.async.wait_group %0;" :: "n"(N) : "memory");
}

// ---------------- init ----------------
__global__ void zero_init_kernel() {
    int i = blockIdx.x * blockDim.x + threadIdx.x;
    if (i < NN * RR) d_cnt[i] = 0;
    if (i < GG * HH) d_pool[i] = 0.0f;
    if (i < GG) d_poolcnt[i] = 0.0f;
}

// ---------------- one-time x split: fp32 -> bf16 hi/lo + fp16 ----------------
__global__ void xsplit_kernel(const float* __restrict__ x) {
    int i = blockIdx.x * blockDim.x + threadIdx.x;
    if (i >= NN * HH / 2) return;
    float2 v = *(const float2*)(x + i * 2);
    uint32_t h, l;
    split2(v.x, v.y, h, l);
    *(uint32_t*)((__nv_bfloat16*)d_x_hi + (size_t)i * 2) = h;
    *(uint32_t*)((__nv_bfloat16*)d_x_lo + (size_t)i * 2) = l;
    __half2 p = __float22half2_rn(v);
    *(__half2*)(d_x16 + (size_t)i * 2) = p;
}

// ---------------- weight prep: transpose + hi/lo split ----------------
__global__ void wprep_kernel(const float* __restrict__ bases,
                             const float* __restrict__ root, int layer) {
    int i = blockIdx.x * blockDim.x + threadIdx.x;
    if (i >= KTOT * NTILE) return;
    int k = i >> 7, n = i & 127;
    float w = (k < 512) ? bases[k * 128 + n] : root[(k - 512) * 128 + n];
    __nv_bfloat16 h = __float2bfloat16(w);
    float hf = __bfloat162float(h);
    __nv_bfloat16 l = __float2bfloat16(w - hf);
    size_t o = (size_t)layer * NTILE * KTOT + (size_t)n * KTOT + k;
    d_wt_hi[o] = h;
    d_wt_lo[o] = l;
}

// ---------------- CSR build ----------------
__global__ void count_kernel(const int* __restrict__ ei, const int* __restrict__ et) {
    int e = blockIdx.x * blockDim.x + threadIdx.x;
    if (e >= EE) return;
    int dst = __ldg(ei + EE + e);
    int t   = __ldg(et + e);
    atomicAdd(&d_cnt[dst * RR + t], 1);
}

// per-node: deg from cnt, invcnt, poolcnt
__global__ void deg_kernel(const int* __restrict__ batch) {
    int n = blockIdx.x * blockDim.x + threadIdx.x;
    if (n >= NN) return;
    const int4* c4 = (const int4*)(d_cnt + n * RR);
    int deg = 0;
    float4* iv = (float4*)(d_invcnt + n * RR);
    #pragma unroll
    for (int q = 0; q < 4; q++) {
        int4 c = c4[q];
        deg += c.x + c.y + c.z + c.w;
        float4 f;
        f.x = 1.0f / (float)(c.x > 1 ? c.x : 1);
        f.y = 1.0f / (float)(c.y > 1 ? c.y : 1);
        f.z = 1.0f / (float)(c.z > 1 ? c.z : 1);
        f.w = 1.0f / (float)(c.w > 1 ? c.w : 1);
        iv[q] = f;
    }
    d_deg[n] = deg;
    atomicAdd(&d_poolcnt[__ldg(batch + n)], 1.0f);
}

// ---------------- hierarchical scan of d_deg -> d_rowptr ----------------
__global__ void partial_kernel() {
    __shared__ int sh[SCAN_B];
    int tid = threadIdx.x;
    int i = blockIdx.x * SCAN_B + tid;
    sh[tid] = (i < NN) ? d_deg[i] : 0;
    __syncthreads();
    for (int off = SCAN_B / 2; off > 0; off >>= 1) {
        if (tid < off) sh[tid] += sh[tid + off];
        __syncthreads();
    }
    if (tid == 0) d_part[blockIdx.x] = sh[0];
}

__global__ void scanpart_kernel() {   // 1 block, 256 threads
    __shared__ int sh[256];
    int tid = threadIdx.x;
    int v = (tid < SCAN_G) ? d_part[tid] : 0;
    sh[tid] = v;
    __syncthreads();
    for (int off = 1; off < 256; off <<= 1) {
        int t = (tid >= off) ? sh[tid - off] : 0;
        __syncthreads();
        sh[tid] += t;
        __syncthreads();
    }
    if (tid < SCAN_G) d_partpre[tid] = sh[tid] - v;   // exclusive
}

__global__ void rowptr_kernel() {
    __shared__ int sh[SCAN_B];
    int tid = threadIdx.x;
    int i = blockIdx.x * SCAN_B + tid;
    int v = (i < NN) ? d_deg[i] : 0;
    sh[tid] = v;
    __syncthreads();
    for (int off = 1; off < SCAN_B; off <<= 1) {
        int t = (tid >= off) ? sh[tid - off] : 0;
        __syncthreads();
        sh[tid] += t;
        __syncthreads();
    }
    if (i < NN) d_rowptr[i] = sh[tid] - v + d_partpre[blockIdx.x];
    if (i == 0) d_rowptr[NN] = EE;
}

// per-node type offsets (cursors for scatter; lower contention than per-node)
__global__ void typeoff_kernel() {
    int n = blockIdx.x * blockDim.x + threadIdx.x;
    if (n >= NN) return;
    int off = d_rowptr[n];
    #pragma unroll
    for (int t = 0; t < RR; t++) {
        d_typeoff[n * RR + t] = off;
        off += d_cnt[n * RR + t];
    }
}

__global__ void scatter_kernel(const int* __restrict__ ei, const int* __restrict__ et) {
    int e = blockIdx.x * blockDim.x + threadIdx.x;
    if (e >= EE) return;
    int src = __ldg(ei + e);
    int dst = __ldg(ei + EE + e);
    int t   = __ldg(et + e);
    int pos = atomicAdd(&d_typeoff[dst * RR + t], 1);
    d_csr[pos] = (unsigned)src | ((unsigned)t << 20);
}

// ---------------- per-layer aggregation (branch-free, MLP-8, no tail) ---------
// one warp per node. Every <=32-edge block goes through the unrolled path with
// a clamped CSR index; invalid lanes contribute zero via the validity factor.
__global__ void agg_kernel(const __half* __restrict__ X16,
                           const float* __restrict__ comp /*[R,NB]*/) {
    __shared__ float4 s_comp4[RR];
    int tid = threadIdx.x;
    if (tid < RR) s_comp4[tid] = *(const float4*)(comp + tid * NB);
    __syncthreads();

    int warp = (blockIdx.x * blockDim.x + tid) >> 5;
    int lane = tid & 31;
    if (warp >= NN) return;

    int beg = d_rowptr[warp];
    int end = d_rowptr[warp + 1];
    float inv_t = (lane < RR) ? d_invcnt[warp * RR + lane] : 0.0f;

    float4 acc[NB];
    #pragma unroll
    for (int b = 0; b < NB; b++) acc[b] = make_float4(0.f, 0.f, 0.f, 0.f);

    const __half* Xl = X16 + lane * 4;

    for (int i = beg; i < end; i += 32) {
        int rem = end - i;                    // >= 1, warp-uniform
        int li = lane < rem ? lane : rem - 1; // clamped index
        unsigned pv = d_csr[i + li];
        #pragma unroll 8
        for (int j = 0; j < 32; j++) {
            unsigned p = __shfl_sync(0xffffffffu, pv, j);
            int src = (int)(p & 0xFFFFFu);
            int t   = (int)(p >> 20);
            float valid = (j < rem) ? 1.0f : 0.0f;
            float ic = __shfl_sync(0xffffffffu, inv_t, t) * valid;
            uint2 raw = *(const uint2*)(Xl + (size_t)src * HH);
            float2 f0 = __half22float2(*(__half2*)&raw.x);
            float2 f1 = __half22float2(*(__half2*)&raw.y);
            float4 cw = s_comp4[t];
            acc[0].x += cw.x * ic * f0.x; acc[0].y += cw.x * ic * f0.y;
            acc[0].z += cw.x * ic * f1.x; acc[0].w += cw.x * ic * f1.y;
            acc[1].x += cw.y * ic * f0.x; acc[1].y += cw.y * ic * f0.y;
            acc[1].z += cw.y * ic * f1.x; acc[1].w += cw.y * ic * f1.y;
            acc[2].x += cw.z * ic * f0.x; acc[2].y += cw.z * ic * f0.y;
            acc[2].z += cw.z * ic * f1.x; acc[2].w += cw.z * ic * f1.y;
            acc[3].x += cw.w * ic * f0.x; acc[3].y += cw.w * ic * f0.y;
            acc[3].z += cw.w * ic * f1.x; acc[3].w += cw.w * ic * f1.y;
        }
    }

    size_t base = (size_t)warp * 512 + lane * 4;
    #pragma unroll
    for (int b = 0; b < NB; b++) {
        uint32_t h0, h1, l0, l1;
        split2(acc[b].x, acc[b].y, h0, l0);
        split2(acc[b].z, acc[b].w, h1, l1);
        *(uint2*)(d_z_hi + base + b * 128) = make_uint2(h0, h1);
        *(uint2*)(d_z_lo + base + b * 128) = make_uint2(l0, l1);
    }
}

// ---------------- tensor-core GEMM: cp.async double-buffered HMMA --------------
// MTILE=64, 2 CTAs/SM. Warp tile 32x32 (2 m-tiles x 4 n-tiles).
__global__ void __launch_bounds__(256, 2)
tc_gemm_kernel(const __nv_bfloat16* __restrict__ Xhi, const __nv_bfloat16* __restrict__ Xlo,
               __half* __restrict__ OUT16,              // fp16 (layers 1,2)
               __nv_bfloat16* __restrict__ OUThi, __nv_bfloat16* __restrict__ OUTlo,
               const float* __restrict__ bias, int relu, int layer,
               int do_pool, const int* __restrict__ batch) {
    extern __shared__ __align__(1024) char smem[];
    uint32_t sb = smem_u32(smem);
    int tid = threadIdx.x;
    int wid = tid >> 5;
    int lane = tid & 31;
    int row0 = blockIdx.x * MTILE;

    const __nv_bfloat16* Whi = d_wt_hi + (size_t)layer * NTILE * KTOT;
    const __nv_bfloat16* Wlo = d_wt_lo + (size_t)layer * NTILE * KTOT;

    // A loader coords: 512 (row,col8) pairs, 2 per thread
    int lrA[2], lcA[2];
    uint32_t ldstA[2];
    #pragma unroll
    for (int i = 0; i < 2; i++) {
        int g = tid + i * 256;
        lrA[i] = g >> 3;
        lcA[i] = (g & 7) * 8;
        ldstA[i] = SW128((uint32_t)(lrA[i] * 128 + lcA[i] * 2));
    }
    // B loader coords: 1024 pairs, 4 per thread
    int lrB[4], lcB[4];
    uint32_t ldstB[4];
    #pragma unroll
    for (int i = 0; i < 4; i++) {
        int g = tid + i * 256;
        lrB[i] = g >> 3;
        lcB[i] = (g & 7) * 8;
        ldstB[i] = SW128((uint32_t)(lrB[i] * 128 + lcB[i] * 2));
    }

    #define LOAD_CHUNK(c, stage)                                                      \
    {                                                                                 \
        uint32_t s0 = sb + (stage) * STAGE_BYTES;                                     \
        _Pragma("unroll")                                                             \
        for (int i = 0; i < 2; i++) {                                                 \
            int gm = row0 + lrA[i];                                                   \
            const __nv_bfloat16 *ah, *al;                                             \
            if ((c) < 8) {                                                            \
                ah = d_z_hi + (size_t)gm * 512 + (c) * KCHUNK + lcA[i];               \
                al = d_z_lo + (size_t)gm * 512 + (c) * KCHUNK + lcA[i];               \
            } else {                                                                  \
                ah = Xhi + (size_t)gm * 128 + ((c) - 8) * KCHUNK + lcA[i];            \
                al = Xlo + (size_t)gm * 128 + ((c) - 8) * KCHUNK + lcA[i];            \
            }                                                                         \
            cp16(s0 + ldstA[i], ah);                                                  \
            cp16(s0 + A_LO_OFF + ldstA[i], al);                                       \
        }                                                                             \
        _Pragma("unroll")                                                             \
        for (int i = 0; i < 4; i++) {                                                 \
            const __nv_bfloat16* bh = Whi + (size_t)lrB[i] * KTOT + (c) * KCHUNK + lcB[i]; \
            const __nv_bfloat16* bl = Wlo + (size_t)lrB[i] * KTOT + (c) * KCHUNK + lcB[i]; \
            cp16(s0 + B_HI_OFF + ldstB[i], bh);                                       \
            cp16(s0 + B_LO_OFF + ldstB[i], bl);                                       \
        }                                                                             \
    }

    int wm = (wid & 1) * 32;          // 0 or 32 (rows)
    int wn = (wid >> 1) * 32;         // 0..96 (cols)

    int sub = lane & 7, g = lane >> 3;
    int a_r = sub + ((g & 1) << 3);
    int a_k = (g >> 1) << 3;
    int b_r = sub + ((g >> 1) << 3);
    int b_k = (g & 1) << 3;

    float acc[2][4][4];
    #pragma unroll
    for (int mt = 0; mt < 2; mt++)
        #pragma unroll
        for (int nt = 0; nt < 4; nt++)
            #pragma unroll
            for (int q = 0; q < 4; q++) acc[mt][nt][q] = 0.0f;

    LOAD_CHUNK(0, 0);
    cp_commit();

    for (int c = 0; c < NCHUNKS; c++) {
        if (c + 1 < NCHUNKS) {
            LOAD_CHUNK(c + 1, (c + 1) & 1);
            cp_commit();
            cp_wait<1>();
        } else {
            cp_wait<0>();
        }
        __syncthreads();

        uint32_t s0 = sb + (c & 1) * STAGE_BYTES;
        #pragma unroll
        for (int ks = 0; ks < 4; ks++) {
            uint32_t ah[2][4], al[2][4], bh[2][4], bl[2][4];
            #pragma unroll
            for (int mt = 0; mt < 2; mt++) {
                uint32_t off = SW128((uint32_t)((wm + mt * 16 + a_r) * 128 + (ks * 16 + a_k) * 2));
                ldsm_x4(ah[mt], s0 + off);
                ldsm_x4(al[mt], s0 + A_LO_OFF + off);
            }
            #pragma unroll
            for (int nt2 = 0; nt2 < 2; nt2++) {
                uint32_t off = SW128((uint32_t)((wn + nt2 * 16 + b_r) * 128 + (ks * 16 + b_k) * 2));
                ldsm_x4(bh[nt2], s0 + B_HI_OFF + off);
                ldsm_x4(bl[nt2], s0 + B_LO_OFF + off);
            }
            #pragma unroll
            for (int mt = 0; mt < 2; mt++)
                #pragma unroll
                for (int nt = 0; nt < 4; nt++) {
                    uint32_t b0h = bh[nt >> 1][(nt & 1) * 2], b1h = bh[nt >> 1][(nt & 1) * 2 + 1];
                    uint32_t b0l = bl[nt >> 1][(nt & 1) * 2], b1l = bl[nt >> 1][(nt & 1) * 2 + 1];
                    mma_bf16(acc[mt][nt], ah[mt], b0h, b1h);
                    mma_bf16(acc[mt][nt], ah[mt], b0l, b1l);
                    mma_bf16(acc[mt][nt], al[mt], b0h, b1h);
                }
        }
        __syncthreads();
    }
    #undef LOAD_CHUNK

    if (!do_pool) {
        #pragma unroll
        for (int mt = 0; mt < 2; mt++) {
            int rr2[2];
            rr2[0] = row0 + wm + mt * 16 + (lane >> 2);
            rr2[1] = rr2[0] + 8;
            #pragma unroll
            for (int nt = 0; nt < 4; nt++) {
                int col = wn + nt * 8 + ((lane & 3) << 1);
                float2 b2 = *(const float2*)(bias + col);
                #pragma unroll
                for (int h2i = 0; h2i < 2; h2i++) {
                    int r = rr2[h2i];
                    if (r >= NN) continue;
                    float2 v;
                    v.x = acc[mt][nt][h2i * 2 + 0] + b2.x;
                    v.y = acc[mt][nt][h2i * 2 + 1] + b2.y;
                    if (relu) { v.x = fmaxf(v.x, 0.f); v.y = fmaxf(v.y, 0.f); }
                    *(__half2*)(OUT16 + (size_t)r * 128 + col) = __float22half2_rn(v);
                    uint32_t h, l;
                    split2(v.x, v.y, h, l);
                    *(uint32_t*)(OUThi + (size_t)r * 128 + col) = h;
                    *(uint32_t*)(OUTlo + (size_t)r * 128 + col) = l;
                }
            }
        }
    } else {
        float pacc[8];
        int curg = -1;
        int colb = wn + ((lane & 3) << 1);
        #pragma unroll
        for (int mt = 0; mt < 2; mt++) {
            #pragma unroll
            for (int h2i = 0; h2i < 2; h2i++) {
                int r = row0 + wm + mt * 16 + (lane >> 2) + h2i * 8;
                if (r >= NN) continue;
                int gph = __ldg(batch + r);
                if (gph != curg) {
                    if (curg >= 0) {
                        #pragma unroll
                        for (int j = 0; j < 4; j++) {
                            atomicAdd(&d_pool[curg * 128 + colb + j * 8], pacc[j * 2]);
                            atomicAdd(&d_pool[curg * 128 + colb + j * 8 + 1], pacc[j * 2 + 1]);
                        }
                    }
                    curg = gph;
                    #pragma unroll
                    for (int j = 0; j < 8; j++) pacc[j] = 0.f;
                }
                #pragma unroll
                for (int nt = 0; nt < 4; nt++) {
                    float2 b2 = *(const float2*)(bias + colb + nt * 8);
                    pacc[nt * 2 + 0] += acc[mt][nt][h2i * 2 + 0] + b2.x;
                    pacc[nt * 2 + 1] += acc[mt][nt][h2i * 2 + 1] + b2.y;
                }
            }
        }
        if (curg >= 0) {
            #pragma unroll
            for (int j = 0; j < 4; j++) {
                atomicAdd(&d_pool[curg * 128 + colb + j * 8], pacc[j * 2]);
                atomicAdd(&d_pool[curg * 128 + colb + j * 8 + 1], pacc[j * 2 + 1]);
            }
        }
    }
}

// ---------------- final ----------------
__global__ void final_kernel(const int* __restrict__ rl,
                             const float* __restrict__ rel_emb,
                             const float* __restrict__ lw,   // [256,2]
                             const float* __restrict__ lb,   // [2]
                             float* __restrict__ out) {
    int t = threadIdx.x;
    if (t >= GG * NC) return;
    int g = t >> 1, c = t & 1;
    float cnt = d_poolcnt[g];
    float invc = 1.0f / (cnt > 1.0f ? cnt : 1.0f);
    const float* re = rel_emb + (size_t)rl[g] * 128;
    float s = 0.f;
    for (int j = 0; j < 128; j++) s += d_pool[g * 128 + j] * invc * lw[j * 2 + c];
    for (int j = 0; j < 128; j++) s += re[j] * lw[(128 + j) * 2 + c];
    out[g * 2 + c] = s + lb[c];
}

// ---------------- launch ----------------
extern "C" void kernel_launch(void* const* d_in, const int* in_sizes, int n_in,
                              void* d_out, int out_size) {
    const float* x      = (const float*)d_in[0];
    const int*   ei     = (const int*)d_in[1];
    const int*   et     = (const int*)d_in[2];
    const int*   batch  = (const int*)d_in[3];
    const int*   rl     = (const int*)d_in[4];
    const float* relemb = (const float*)d_in[6];
    const float* bases[3] = {(const float*)d_in[7],  (const float*)d_in[11], (const float*)d_in[15]};
    const float* comp[3]  = {(const float*)d_in[8],  (const float*)d_in[12], (const float*)d_in[16]};
    const float* root[3]  = {(const float*)d_in[9],  (const float*)d_in[13], (const float*)d_in[17]};
    const float* bias[3]  = {(const float*)d_in[10], (const float*)d_in[14], (const float*)d_in[18]};
    const float* lin_w  = (const float*)d_in[19];
    const float* lin_b  = (const float*)d_in[20];
    float* out = (float*)d_out;

    cudaFuncSetAttribute(tc_gemm_kernel, cudaFuncAttributeMaxDynamicSharedMemorySize, GEMM_SMEM);

    void *p_x16, *p_h116, *p_h216;
    void *p_xh, *p_xl, *p_h1h, *p_h1l, *p_h2h, *p_h2l;
    cudaGetSymbolAddress(&p_x16, d_x16);
    cudaGetSymbolAddress(&p_h116, d_h1_16);
    cudaGetSymbolAddress(&p_h216, d_h2_16);
    cudaGetSymbolAddress(&p_xh, d_x_hi);
    cudaGetSymbolAddress(&p_xl, d_x_lo);
    cudaGetSymbolAddress(&p_h1h, d_h1_hi);
    cudaGetSymbolAddress(&p_h1l, d_h1_lo);
    cudaGetSymbolAddress(&p_h2h, d_h2_hi);
    cudaGetSymbolAddress(&p_h2l, d_h2_lo);

    const int TB = 256;
    zero_init_kernel<<<(NN * RR + TB - 1) / TB, TB>>>();
    count_kernel<<<(EE + TB - 1) / TB, TB>>>(ei, et);
    deg_kernel<<<(NN + TB - 1) / TB, TB>>>(batch);
    partial_kernel<<<SCAN_G, SCAN_B>>>();
    scanpart_kernel<<<1, 256>>>();
    rowptr_kernel<<<SCAN_G, SCAN_B>>>();
    typeoff_kernel<<<(NN + TB - 1) / TB, TB>>>();
    scatter_kernel<<<(EE + TB - 1) / TB, TB>>>(ei, et);
    xsplit_kernel<<<(NN * HH / 2 + TB - 1) / TB, TB>>>(x);

    int wpBlocks = (KTOT * NTILE + TB - 1) / TB;
    wprep_kernel<<<wpBlocks, TB>>>(bases[0], root[0], 0);
    wprep_kernel<<<wpBlocks, TB>>>(bases[1], root[1], 1);
    wprep_kernel<<<wpBlocks, TB>>>(bases[2], root[2], 2);

    int aggBlocks = (NN * 32 + TB - 1) / TB;

    // layer 1
    agg_kernel<<<aggBlocks, TB>>>((const __half*)p_x16, comp[0]);
    tc_gemm_kernel<<<GEMM_GRID, 256, GEMM_SMEM>>>(
        (const __nv_bfloat16*)p_xh, (const __nv_bfloat16*)p_xl,
        (__half*)p_h116, (__nv_bfloat16*)p_h1h, (__nv_bfloat16*)p_h1l,
        bias[0], 1, 0, 0, batch);
    // layer 2
    agg_kernel<<<aggBlocks, TB>>>((const __half*)p_h116, comp[1]);
    tc_gemm_kernel<<<GEMM_GRID, 256, GEMM_SMEM>>>(
        (const __nv_bfloat16*)p_h1h, (const __nv_bfloat16*)p_h1l,
        (__half*)p_h216, (__nv_bfloat16*)p_h2h, (__nv_bfloat16*)p_h2l,
        bias[1], 1, 1, 0, batch);
    // layer 3: pools directly
    agg_kernel<<<aggBlocks, TB>>>((const __half*)p_h216, comp[2]);
    tc_gemm_kernel<<<GEMM_GRID, 256, GEMM_SMEM>>>(
        (const __nv_bfloat16*)p_h2h, (const __nv_bfloat16*)p_h2l,
        (__half*)nullptr, (__nv_bfloat16*)nullptr, (__nv_bfloat16*)nullptr,
        bias[2], 0, 2, 1, batch);

    final_kernel<<<1, 128>>>(rl, relemb, lin_w, lin_b, out);
}

// round 16
// speedup vs baseline: 1.0964x; 1.0964x over previous
#include <cuda_runtime.h>
#include <cuda_bf16.h>
#include <cuda_fp16.h>
#include <cstdint>

// Problem constants
#define NN   50000
#define NPAD 50048
#define EE   1600000
#define RR   16
#define NB   4
#define HH   128
#define GG   64
#define NC   2

#define KTOT 640
#define MTILE 128
#define NTILE 128
#define KCHUNK 64
#define NCHUNKS 10
#define GEMM_GRID ((NN + MTILE - 1) / MTILE)   // 391
#define STAGE_BYTES 65536
#define NSTAGE 3
#define GEMM_SMEM (NSTAGE * STAGE_BYTES)       // 192KB

#define SCAN_B 256
#define SCAN_G ((NN + SCAN_B - 1) / SCAN_B)    // 196

// ---------------- device scratch (static, no allocs) ----------------
__device__ unsigned int d_csr[EE];
__device__ int   d_rowptr[NN + 1];
__device__ int   d_deg[NN];
__device__ int   d_typeoff[NN * RR];
__device__ int   d_cnt[NN * RR];
__device__ float d_invcnt[NN * RR];
__device__ int   d_part[SCAN_G];
__device__ int   d_partpre[SCAN_G];
__device__ float d_pool[GG * HH];
__device__ float d_poolcnt[GG];
// fp16 gather mirrors
__device__ __half d_x16[(size_t)NPAD * HH];
__device__ __half d_h1_16[(size_t)NPAD * HH];
__device__ __half d_h2_16[(size_t)NPAD * HH];
// pre-split bf16 operands (padded rows)
__device__ __nv_bfloat16 d_z_hi[(size_t)NPAD * 512];
__device__ __nv_bfloat16 d_z_lo[(size_t)NPAD * 512];
__device__ __nv_bfloat16 d_x_hi[(size_t)NPAD * HH];
__device__ __nv_bfloat16 d_x_lo[(size_t)NPAD * HH];
__device__ __nv_bfloat16 d_h1_hi[(size_t)NPAD * HH];
__device__ __nv_bfloat16 d_h1_lo[(size_t)NPAD * HH];
__device__ __nv_bfloat16 d_h2_hi[(size_t)NPAD * HH];
__device__ __nv_bfloat16 d_h2_lo[(size_t)NPAD * HH];
// transposed + hi/lo split weights: [layer][n(128)][k(640)]
__device__ __nv_bfloat16 d_wt_hi[3 * NTILE * KTOT];
__device__ __nv_bfloat16 d_wt_lo[3 * NTILE * KTOT];

// ---------------- helpers ----------------
__device__ __forceinline__ uint32_t smem_u32(const void* p) {
    uint32_t a;
    asm("{ .reg .u64 t; cvta.to.shared.u64 t, %1; cvt.u32.u64 %0, t; }" : "=r"(a) : "l"(p));
    return a;
}
#define SW128(o) ((o) ^ (((o) >> 3) & 0x70))

__device__ __forceinline__ void split2(float a, float b, uint32_t& hi, uint32_t& lo) {
    __nv_bfloat16 ha = __float2bfloat16(a), hb = __float2bfloat16(b);
    float fa = __bfloat162float(ha), fb = __bfloat162float(hb);
    __nv_bfloat16 la = __float2bfloat16(a - fa), lb = __float2bfloat16(b - fb);
    hi = (uint32_t)__bfloat16_as_ushort(ha) | ((uint32_t)__bfloat16_as_ushort(hb) << 16);
    lo = (uint32_t)__bfloat16_as_ushort(la) | ((uint32_t)__bfloat16_as_ushort(lb) << 16);
}

__device__ __forceinline__ void ldsm_x4(uint32_t* r, uint32_t addr) {
    asm volatile("ldmatrix.sync.aligned.m8n8.x4.shared.b16 {%0,%1,%2,%3}, [%4];"
                 : "=r"(r[0]), "=r"(r[1]), "=r"(r[2]), "=r"(r[3]) : "r"(addr));
}
__device__ __forceinline__ void mma_bf16(float* d, const uint32_t* a, uint32_t b0, uint32_t b1) {
    asm volatile(
        "mma.sync.aligned.m16n8k16.row.col.f32.bf16.bf16.f32 "
        "{%0,%1,%2,%3}, {%4,%5,%6,%7}, {%8,%9}, {%0,%1,%2,%3};"
        : "+f"(d[0]), "+f"(d[1]), "+f"(d[2]), "+f"(d[3])
        : "r"(a[0]), "r"(a[1]), "r"(a[2]), "r"(a[3]), "r"(b0), "r"(b1));
}
__device__ __forceinline__ void cp16(uint32_t smem_dst, const void* gsrc) {
    asm volatile("cp.async.cg.shared.global [%0], [%1], 16;" :: "r"(smem_dst), "l"(gsrc));
}
__device__ __forceinline__ void cp_commit() {
    asm volatile("cp.async.commit_group;" ::: "memory");
}
template<int N> __device__ __forceinline__ void cp_wait() {
    asm volatile("cp.async.wait_group %0;" :: "n"(N) : "memory");
}

// ---------------- init ----------------
__global__ void zero_init_kernel() {
    int i = blockIdx.x * blockDim.x + threadIdx.x;
    if (i < NN * RR) d_cnt[i] = 0;
    if (i < GG * HH) d_pool[i] = 0.0f;
    if (i < GG) d_poolcnt[i] = 0.0f;
}

// ---------------- one-time x split: fp32 -> bf16 hi/lo + fp16 ----------------
__global__ void xsplit_kernel(const float* __restrict__ x) {
    int i = blockIdx.x * blockDim.x + threadIdx.x;
    if (i >= NN * HH / 2) return;
    float2 v = *(const float2*)(x + i * 2);
    uint32_t h, l;
    split2(v.x, v.y, h, l);
    *(uint32_t*)((__nv_bfloat16*)d_x_hi + (size_t)i * 2) = h;
    *(uint32_t*)((__nv_bfloat16*)d_x_lo + (size_t)i * 2) = l;
    __half2 p = __float22half2_rn(v);
    *(__half2*)(d_x16 + (size_t)i * 2) = p;
}

// ---------------- weight prep: transpose + hi/lo split ----------------
__global__ void wprep_kernel(const float* __restrict__ bases,
                             const float* __restrict__ root, int layer) {
    int i = blockIdx.x * blockDim.x + threadIdx.x;
    if (i >= KTOT * NTILE) return;
    int k = i >> 7, n = i & 127;
    float w = (k < 512) ? bases[k * 128 + n] : root[(k - 512) * 128 + n];
    __nv_bfloat16 h = __float2bfloat16(w);
    float hf = __bfloat162float(h);
    __nv_bfloat16 l = __float2bfloat16(w - hf);
    size_t o = (size_t)layer * NTILE * KTOT + (size_t)n * KTOT + k;
    d_wt_hi[o] = h;
    d_wt_lo[o] = l;
}

// ---------------- CSR build ----------------
__global__ void count_kernel(const int* __restrict__ ei, const int* __restrict__ et) {
    int e = blockIdx.x * blockDim.x + threadIdx.x;
    if (e >= EE) return;
    int dst = __ldg(ei + EE + e);
    int t   = __ldg(et + e);
    atomicAdd(&d_cnt[dst * RR + t], 1);
}

// per-node: deg from cnt, invcnt, poolcnt
__global__ void deg_kernel(const int* __restrict__ batch) {
    int n = blockIdx.x * blockDim.x + threadIdx.x;
    if (n >= NN) return;
    const int4* c4 = (const int4*)(d_cnt + n * RR);
    int deg = 0;
    float4* iv = (float4*)(d_invcnt + n * RR);
    #pragma unroll
    for (int q = 0; q < 4; q++) {
        int4 c = c4[q];
        deg += c.x + c.y + c.z + c.w;
        float4 f;
        f.x = 1.0f / (float)(c.x > 1 ? c.x : 1);
        f.y = 1.0f / (float)(c.y > 1 ? c.y : 1);
        f.z = 1.0f / (float)(c.z > 1 ? c.z : 1);
        f.w = 1.0f / (float)(c.w > 1 ? c.w : 1);
        iv[q] = f;
    }
    d_deg[n] = deg;
    atomicAdd(&d_poolcnt[__ldg(batch + n)], 1.0f);
}

// ---------------- hierarchical scan of d_deg -> d_rowptr ----------------
__global__ void partial_kernel() {
    __shared__ int sh[SCAN_B];
    int tid = threadIdx.x;
    int i = blockIdx.x * SCAN_B + tid;
    sh[tid] = (i < NN) ? d_deg[i] : 0;
    __syncthreads();
    for (int off = SCAN_B / 2; off > 0; off >>= 1) {
        if (tid < off) sh[tid] += sh[tid + off];
        __syncthreads();
    }
    if (tid == 0) d_part[blockIdx.x] = sh[0];
}

__global__ void scanpart_kernel() {   // 1 block, 256 threads
    __shared__ int sh[256];
    int tid = threadIdx.x;
    int v = (tid < SCAN_G) ? d_part[tid] : 0;
    sh[tid] = v;
    __syncthreads();
    for (int off = 1; off < 256; off <<= 1) {
        int t = (tid >= off) ? sh[tid - off] : 0;
        __syncthreads();
        sh[tid] += t;
        __syncthreads();
    }
    if (tid < SCAN_G) d_partpre[tid] = sh[tid] - v;   // exclusive
}

__global__ void rowptr_kernel() {
    __shared__ int sh[SCAN_B];
    int tid = threadIdx.x;
    int i = blockIdx.x * SCAN_B + tid;
    int v = (i < NN) ? d_deg[i] : 0;
    sh[tid] = v;
    __syncthreads();
    for (int off = 1; off < SCAN_B; off <<= 1) {
        int t = (tid >= off) ? sh[tid - off] : 0;
        __syncthreads();
        sh[tid] += t;
        __syncthreads();
    }
    if (i < NN) d_rowptr[i] = sh[tid] - v + d_partpre[blockIdx.x];
    if (i == 0) d_rowptr[NN] = EE;
}

// per-node type offsets (cursors for scatter; lower contention than per-node)
__global__ void typeoff_kernel() {
    int n = blockIdx.x * blockDim.x + threadIdx.x;
    if (n >= NN) return;
    int off = d_rowptr[n];
    #pragma unroll
    for (int t = 0; t < RR; t++) {
        d_typeoff[n * RR + t] = off;
        off += d_cnt[n * RR + t];
    }
}

__global__ void scatter_kernel(const int* __restrict__ ei, const int* __restrict__ et) {
    int e = blockIdx.x * blockDim.x + threadIdx.x;
    if (e >= EE) return;
    int src = __ldg(ei + e);
    int dst = __ldg(ei + EE + e);
    int t   = __ldg(et + e);
    int pos = atomicAdd(&d_typeoff[dst * RR + t], 1);
    d_csr[pos] = (unsigned)src | ((unsigned)t << 20);
}

// ---------------- per-layer aggregation (branch-free, MLP-8) ------------------
// one warp per node. CSR entries loaded coalesced (32 at a time), broadcast by
// shuffle; per-edge weighting, no branches in the inner loop.
__global__ void agg_kernel(const __half* __restrict__ X16,
                           const float* __restrict__ comp /*[R,NB]*/) {
    __shared__ float4 s_comp4[RR];
    int tid = threadIdx.x;
    if (tid < RR) s_comp4[tid] = *(const float4*)(comp + tid * NB);
    __syncthreads();

    int warp = (blockIdx.x * blockDim.x + tid) >> 5;
    int lane = tid & 31;
    if (warp >= NN) return;

    int beg = d_rowptr[warp];
    int end = d_rowptr[warp + 1];
    float inv_t = (lane < RR) ? d_invcnt[warp * RR + lane] : 0.0f;

    float4 acc[NB];
    #pragma unroll
    for (int b = 0; b < NB; b++) acc[b] = make_float4(0.f, 0.f, 0.f, 0.f);

    const __half* Xl = X16 + lane * 4;

    int i = beg;
    // full blocks of 32 edges: one coalesced csr load per block
    for (; i + 32 <= end; i += 32) {
        unsigned pv = d_csr[i + lane];
        #pragma unroll 8
        for (int j = 0; j < 32; j++) {
            unsigned p = __shfl_sync(0xffffffffu, pv, j);
            int src = (int)(p & 0xFFFFFu);
            int t   = (int)(p >> 20);
            float ic = __shfl_sync(0xffffffffu, inv_t, t);
            uint2 raw = *(const uint2*)(Xl + (size_t)src * HH);
            float2 f0 = __half22float2(*(__half2*)&raw.x);
            float2 f1 = __half22float2(*(__half2*)&raw.y);
            float4 cw = s_comp4[t];
            acc[0].x += cw.x * ic * f0.x; acc[0].y += cw.x * ic * f0.y;
            acc[0].z += cw.x * ic * f1.x; acc[0].w += cw.x * ic * f1.y;
            acc[1].x += cw.y * ic * f0.x; acc[1].y += cw.y * ic * f0.y;
            acc[1].z += cw.y * ic * f1.x; acc[1].w += cw.y * ic * f1.y;
            acc[2].x += cw.z * ic * f0.x; acc[2].y += cw.z * ic * f0.y;
            acc[2].z += cw.z * ic * f1.x; acc[2].w += cw.z * ic * f1.y;
            acc[3].x += cw.w * ic * f0.x; acc[3].y += cw.w * ic * f0.y;
            acc[3].z += cw.w * ic * f1.x; acc[3].w += cw.w * ic * f1.y;
        }
    }
    // tail (< 32 edges)
    for (; i < end; i++) {
        unsigned p = d_csr[i];
        int src = (int)(p & 0xFFFFFu);
        int t   = (int)(p >> 20);
        float ic = __shfl_sync(0xffffffffu, inv_t, t);
        uint2 raw = *(const uint2*)(Xl + (size_t)src * HH);
        float2 f0 = __half22float2(*(__half2*)&raw.x);
        float2 f1 = __half22float2(*(__half2*)&raw.y);
        float4 cw = s_comp4[t];
        acc[0].x += cw.x * ic * f0.x; acc[0].y += cw.x * ic * f0.y;
        acc[0].z += cw.x * ic * f1.x; acc[0].w += cw.x * ic * f1.y;
        acc[1].x += cw.y * ic * f0.x; acc[1].y += cw.y * ic * f0.y;
        acc[1].z += cw.y * ic * f1.x; acc[1].w += cw.y * ic * f1.y;
        acc[2].x += cw.z * ic * f0.x; acc[2].y += cw.z * ic * f0.y;
        acc[2].z += cw.z * ic * f1.x; acc[2].w += cw.z * ic * f1.y;
        acc[3].x += cw.w * ic * f0.x; acc[3].y += cw.w * ic * f0.y;
        acc[3].z += cw.w * ic * f1.x; acc[3].w += cw.w * ic * f1.y;
    }

    size_t base = (size_t)warp * 512 + lane * 4;
    #pragma unroll
    for (int b = 0; b < NB; b++) {
        uint32_t h0, h1, l0, l1;
        split2(acc[b].x, acc[b].y, h0, l0);
        split2(acc[b].z, acc[b].w, h1, l1);
        *(uint2*)(d_z_hi + base + b * 128) = make_uint2(h0, h1);
        *(uint2*)(d_z_lo + base + b * 128) = make_uint2(l0, l1);
    }
}

// ---------------- tensor-core GEMM: cp.async 3-stage pipelined HMMA ------------
// stage layout: Ah[16K] Al[16K] Bh[16K] Bl[16K]; tiles [128 rows][64 k] bf16,
// row stride 128B, SW128 swizzle. Prefetch depth 2.
__global__ void __launch_bounds__(256, 1)
tc_gemm_kernel(const __nv_bfloat16* __restrict__ Xhi, const __nv_bfloat16* __restrict__ Xlo,
               __half* __restrict__ OUT16,              // fp16 (layers 1,2)
               __nv_bfloat16* __restrict__ OUThi, __nv_bfloat16* __restrict__ OUTlo,
               const float* __restrict__ bias, int relu, int layer,
               int do_pool, const int* __restrict__ batch) {
    extern __shared__ __align__(1024) char smem[];
    uint32_t sb = smem_u32(smem);
    int tid = threadIdx.x;
    int wid = tid >> 5;
    int lane = tid & 31;
    int row0 = blockIdx.x * MTILE;

    const __nv_bfloat16* Whi = d_wt_hi + (size_t)layer * NTILE * KTOT;
    const __nv_bfloat16* Wlo = d_wt_lo + (size_t)layer * NTILE * KTOT;

    int lr[4], lc[4];
    uint32_t ldst[4];
    #pragma unroll
    for (int i = 0; i < 4; i++) {
        int g = tid + i * 256;
        lr[i] = g >> 3;
        lc[i] = (g & 7) * 8;
        ldst[i] = SW128((uint32_t)(lr[i] * 128 + lc[i] * 2));
    }

    #define LOAD_CHUNK(c, stage)                                                      \
    {                                                                                 \
        uint32_t s0 = sb + (stage) * STAGE_BYTES;                                     \
        _Pragma("unroll")                                                             \
        for (int i = 0; i < 4; i++) {                                                 \
            int gm = row0 + lr[i];                                                    \
            const __nv_bfloat16 *ah, *al;                                             \
            if ((c) < 8) {                                                            \
                ah = d_z_hi + (size_t)gm * 512 + (c) * KCHUNK + lc[i];                \
                al = d_z_lo + (size_t)gm * 512 + (c) * KCHUNK + lc[i];                \
            } else {                                                                  \
                ah = Xhi + (size_t)gm * 128 + ((c) - 8) * KCHUNK + lc[i];             \
                al = Xlo + (size_t)gm * 128 + ((c) - 8) * KCHUNK + lc[i];             \
            }                                                                         \
            cp16(s0 + ldst[i], ah);                                                   \
            cp16(s0 + 16384 + ldst[i], al);                                           \
            const __nv_bfloat16* bh = Whi + (size_t)lr[i] * KTOT + (c) * KCHUNK + lc[i]; \
            const __nv_bfloat16* bl = Wlo + (size_t)lr[i] * KTOT + (c) * KCHUNK + lc[i]; \
            cp16(s0 + 32768 + ldst[i], bh);                                           \
            cp16(s0 + 49152 + ldst[i], bl);                                           \
        }                                                                             \
    }

    int wm = (wid & 1) * 64;
    int wn = (wid >> 1) * 32;

    int sub = lane & 7, g = lane >> 3;
    int a_r = sub + ((g & 1) << 3);
    int a_k = (g >> 1) << 3;
    int b_r = sub + ((g >> 1) << 3);
    int b_k = (g & 1) << 3;

    float acc[4][4][4];
    #pragma unroll
    for (int mt = 0; mt < 4; mt++)
        #pragma unroll
        for (int nt = 0; nt < 4; nt++)
            #pragma unroll
            for (int q = 0; q < 4; q++) acc[mt][nt][q] = 0.0f;

    LOAD_CHUNK(0, 0);
    cp_commit();
    LOAD_CHUNK(1, 1);
    cp_commit();

    for (int c = 0; c < NCHUNKS; c++) {
        if (c + 2 < NCHUNKS) {
            LOAD_CHUNK(c + 2, (c + 2) % NSTAGE);
            cp_commit();
            cp_wait<2>();
        } else if (c + 1 < NCHUNKS) {
            cp_wait<1>();
        } else {
            cp_wait<0>();
        }
        __syncthreads();

        uint32_t s0 = sb + (c % NSTAGE) * STAGE_BYTES;
        #pragma unroll
        for (int ks = 0; ks < 4; ks++) {
            uint32_t ah[4][4], al[4][4], bh[2][4], bl[2][4];
            #pragma unroll
            for (int mt = 0; mt < 4; mt++) {
                uint32_t off = SW128((uint32_t)((wm + mt * 16 + a_r) * 128 + (ks * 16 + a_k) * 2));
                ldsm_x4(ah[mt], s0 + off);
                ldsm_x4(al[mt], s0 + 16384 + off);
            }
            #pragma unroll
            for (int nt2 = 0; nt2 < 2; nt2++) {
                uint32_t off = SW128((uint32_t)((wn + nt2 * 16 + b_r) * 128 + (ks * 16 + b_k) * 2));
                ldsm_x4(bh[nt2], s0 + 32768 + off);
                ldsm_x4(bl[nt2], s0 + 49152 + off);
            }
            #pragma unroll
            for (int mt = 0; mt < 4; mt++)
                #pragma unroll
                for (int nt = 0; nt < 4; nt++) {
                    uint32_t b0h = bh[nt >> 1][(nt & 1) * 2], b1h = bh[nt >> 1][(nt & 1) * 2 + 1];
                    uint32_t b0l = bl[nt >> 1][(nt & 1) * 2], b1l = bl[nt >> 1][(nt & 1) * 2 + 1];
                    mma_bf16(acc[mt][nt], ah[mt], b0h, b1h);
                    mma_bf16(acc[mt][nt], ah[mt], b0l, b1l);
                    mma_bf16(acc[mt][nt], al[mt], b0h, b1h);
                }
        }
        __syncthreads();
    }
    #undef LOAD_CHUNK

    if (!do_pool) {
        #pragma unroll
        for (int mt = 0; mt < 4; mt++) {
            int rr2[2];
            rr2[0] = row0 + wm + mt * 16 + (lane >> 2);
            rr2[1] = rr2[0] + 8;
            #pragma unroll
            for (int nt = 0; nt < 4; nt++) {
                int col = wn + nt * 8 + ((lane & 3) << 1);
                float2 b2 = *(const float2*)(bias + col);
                #pragma unroll
                for (int h2i = 0; h2i < 2; h2i++) {
                    int r = rr2[h2i];
                    if (r >= NN) continue;
                    float2 v;
                    v.x = acc[mt][nt][h2i * 2 + 0] + b2.x;
                    v.y = acc[mt][nt][h2i * 2 + 1] + b2.y;
                    if (relu) { v.x = fmaxf(v.x, 0.f); v.y = fmaxf(v.y, 0.f); }
                    *(__half2*)(OUT16 + (size_t)r * 128 + col) = __float22half2_rn(v);
                    uint32_t h, l;
                    split2(v.x, v.y, h, l);
                    *(uint32_t*)(OUThi + (size_t)r * 128 + col) = h;
                    *(uint32_t*)(OUTlo + (size_t)r * 128 + col) = l;
                }
            }
        }
    } else {
        float pacc[8];
        int curg = -1;
        int colb = wn + ((lane & 3) << 1);
        #pragma unroll
        for (int mt = 0; mt < 4; mt++) {
            #pragma unroll
            for (int h2i = 0; h2i < 2; h2i++) {
                int r = row0 + wm + mt * 16 + (lane >> 2) + h2i * 8;
                if (r >= NN) continue;
                int gph = __ldg(batch + r);
                if (gph != curg) {
                    if (curg >= 0) {
                        #pragma unroll
                        for (int j = 0; j < 4; j++) {
                            atomicAdd(&d_pool[curg * 128 + colb + j * 8], pacc[j * 2]);
                            atomicAdd(&d_pool[curg * 128 + colb + j * 8 + 1], pacc[j * 2 + 1]);
                        }
                    }
                    curg = gph;
                    #pragma unroll
                    for (int j = 0; j < 8; j++) pacc[j] = 0.f;
                }
                #pragma unroll
                for (int nt = 0; nt < 4; nt++) {
                    float2 b2 = *(const float2*)(bias + colb + nt * 8);
                    pacc[nt * 2 + 0] += acc[mt][nt][h2i * 2 + 0] + b2.x;
                    pacc[nt * 2 + 1] += acc[mt][nt][h2i * 2 + 1] + b2.y;
                }
            }
        }
        if (curg >= 0) {
            #pragma unroll
            for (int j = 0; j < 4; j++) {
                atomicAdd(&d_pool[curg * 128 + colb + j * 8], pacc[j * 2]);
                atomicAdd(&d_pool[curg * 128 + colb + j * 8 + 1], pacc[j * 2 + 1]);
            }
        }
    }
}

// ---------------- final ----------------
__global__ void final_kernel(const int* __restrict__ rl,
                             const float* __restrict__ rel_emb,
                             const float* __restrict__ lw,   // [256,2]
                             const float* __restrict__ lb,   // [2]
                             float* __restrict__ out) {
    int t = threadIdx.x;
    if (t >= GG * NC) return;
    int g = t >> 1, c = t & 1;
    float cnt = d_poolcnt[g];
    float invc = 1.0f / (cnt > 1.0f ? cnt : 1.0f);
    const float* re = rel_emb + (size_t)rl[g] * 128;
    float s = 0.f;
    for (int j = 0; j < 128; j++) s += d_pool[g * 128 + j] * invc * lw[j * 2 + c];
    for (int j = 0; j < 128; j++) s += re[j] * lw[(128 + j) * 2 + c];
    out[g * 2 + c] = s + lb[c];
}

// ---------------- launch ----------------
extern "C" void kernel_launch(void* const* d_in, const int* in_sizes, int n_in,
                              void* d_out, int out_size) {
    const float* x      = (const float*)d_in[0];
    const int*   ei     = (const int*)d_in[1];
    const int*   et     = (const int*)d_in[2];
    const int*   batch  = (const int*)d_in[3];
    const int*   rl     = (const int*)d_in[4];
    const float* relemb = (const float*)d_in[6];
    const float* bases[3] = {(const float*)d_in[7],  (const float*)d_in[11], (const float*)d_in[15]};
    const float* comp[3]  = {(const float*)d_in[8],  (const float*)d_in[12], (const float*)d_in[16]};
    const float* root[3]  = {(const float*)d_in[9],  (const float*)d_in[13], (const float*)d_in[17]};
    const float* bias[3]  = {(const float*)d_in[10], (const float*)d_in[14], (const float*)d_in[18]};
    const float* lin_w  = (const float*)d_in[19];
    const float* lin_b  = (const float*)d_in[20];
    float* out = (float*)d_out;

    cudaFuncSetAttribute(tc_gemm_kernel, cudaFuncAttributeMaxDynamicSharedMemorySize, GEMM_SMEM);

    void *p_x16, *p_h116, *p_h216;
    void *p_xh, *p_xl, *p_h1h, *p_h1l, *p_h2h, *p_h2l;
    cudaGetSymbolAddress(&p_x16, d_x16);
    cudaGetSymbolAddress(&p_h116, d_h1_16);
    cudaGetSymbolAddress(&p_h216, d_h2_16);
    cudaGetSymbolAddress(&p_xh, d_x_hi);
    cudaGetSymbolAddress(&p_xl, d_x_lo);
    cudaGetSymbolAddress(&p_h1h, d_h1_hi);
    cudaGetSymbolAddress(&p_h1l, d_h1_lo);
    cudaGetSymbolAddress(&p_h2h, d_h2_hi);
    cudaGetSymbolAddress(&p_h2l, d_h2_lo);

    const int TB = 256;
    zero_init_kernel<<<(NN * RR + TB - 1) / TB, TB>>>();
    count_kernel<<<(EE + TB - 1) / TB, TB>>>(ei, et);
    deg_kernel<<<(NN + TB - 1) / TB, TB>>>(batch);
    partial_kernel<<<SCAN_G, SCAN_B>>>();
    scanpart_kernel<<<1, 256>>>();
    rowptr_kernel<<<SCAN_G, SCAN_B>>>();
    typeoff_kernel<<<(NN + TB - 1) / TB, TB>>>();
    scatter_kernel<<<(EE + TB - 1) / TB, TB>>>(ei, et);
    xsplit_kernel<<<(NN * HH / 2 + TB - 1) / TB, TB>>>(x);

    int wpBlocks = (KTOT * NTILE + TB - 1) / TB;
    wprep_kernel<<<wpBlocks, TB>>>(bases[0], root[0], 0);
    wprep_kernel<<<wpBlocks, TB>>>(bases[1], root[1], 1);
    wprep_kernel<<<wpBlocks, TB>>>(bases[2], root[2], 2);

    int aggBlocks = (NN * 32 + TB - 1) / TB;

    // layer 1
    agg_kernel<<<aggBlocks, TB>>>((const __half*)p_x16, comp[0]);
    tc_gemm_kernel<<<GEMM_GRID, 256, GEMM_SMEM>>>(
        (const __nv_bfloat16*)p_xh, (const __nv_bfloat16*)p_xl,
        (__half*)p_h116, (__nv_bfloat16*)p_h1h, (__nv_bfloat16*)p_h1l,
        bias[0], 1, 0, 0, batch);
    // layer 2
    agg_kernel<<<aggBlocks, TB>>>((const __half*)p_h116, comp[1]);
    tc_gemm_kernel<<<GEMM_GRID, 256, GEMM_SMEM>>>(
        (const __nv_bfloat16*)p_h1h, (const __nv_bfloat16*)p_h1l,
        (__half*)p_h216, (__nv_bfloat16*)p_h2h, (__nv_bfloat16*)p_h2l,
        bias[1], 1, 1, 0, batch);
    // layer 3: pools directly
    agg_kernel<<<aggBlocks, TB>>>((const __half*)p_h216, comp[2]);
    tc_gemm_kernel<<<GEMM_GRID, 256, GEMM_SMEM>>>(
        (const __nv_bfloat16*)p_h2h, (const __nv_bfloat16*)p_h2l,
        (__half*)nullptr, (__nv_bfloat16*)nullptr, (__nv_bfloat16*)nullptr,
        bias[2], 0, 2, 1, batch);

    final_kernel<<<1, 128>>>(rl, relemb, lin_w, lin_b, out);
}

// round 17
// speedup vs baseline: 1.4862x; 1.3556x over previous
#include <cuda_runtime.h>
#include <cuda_bf16.h>
#include <cuda_fp16.h>
#include <cstdint>

// Problem constants
#define NN   50000
#define NPAD 50048
#define EE   1600000
#define RR   16
#define NB   4
#define HH   128
#define GG   64
#define NC   2

#define KTOT 640
#define MTILE 128
#define NTILE 128
#define KCHUNK 64
#define NCHUNKS 10
#define GEMM_GRID ((NN + MTILE - 1) / MTILE)   // 391
// stage: A(16K) B(16K) fp16
#define B_OFF 16384
#define STAGE_BYTES 32768
#define GEMM_SMEM (2 * STAGE_BYTES)            // 64KB -> 2 CTAs/SM

#define SCAN_B 256
#define SCAN_G ((NN + SCAN_B - 1) / SCAN_B)    // 196

// ---------------- device scratch (static, no allocs) ----------------
__device__ unsigned int d_csr[EE];
__device__ int   d_rowptr[NN + 1];
__device__ int   d_deg[NN];
__device__ int   d_typeoff[NN * RR];
__device__ int   d_cnt[NN * RR];
__device__ float d_invcnt[NN * RR];
__device__ int   d_part[SCAN_G];
__device__ int   d_partpre[SCAN_G];
__device__ float d_pool[GG * HH];
__device__ float d_poolcnt[GG];
// fp16 features (gather mirrors AND GEMM operands)
__device__ __half d_x16[(size_t)NPAD * HH];
__device__ __half d_h1_16[(size_t)NPAD * HH];
__device__ __half d_h2_16[(size_t)NPAD * HH];
// fp16 aggregated basis features
__device__ __half d_z16[(size_t)NPAD * 512];
// fp16 transposed weights: [layer][n(128)][k(640)]
__device__ __half d_wt16[3 * NTILE * KTOT];

// ---------------- helpers ----------------
__device__ __forceinline__ uint32_t smem_u32(const void* p) {
    uint32_t a;
    asm("{ .reg .u64 t; cvta.to.shared.u64 t, %1; cvt.u32.u64 %0, t; }" : "=r"(a) : "l"(p));
    return a;
}
#define SW128(o) ((o) ^ (((o) >> 3) & 0x70))

__device__ __forceinline__ void ldsm_x4(uint32_t* r, uint32_t addr) {
    asm volatile("ldmatrix.sync.aligned.m8n8.x4.shared.b16 {%0,%1,%2,%3}, [%4];"
                 : "=r"(r[0]), "=r"(r[1]), "=r"(r[2]), "=r"(r[3]) : "r"(addr));
}
__device__ __forceinline__ void mma_f16(float* d, const uint32_t* a, uint32_t b0, uint32_t b1) {
    asm volatile(
        "mma.sync.aligned.m16n8k16.row.col.f32.f16.f16.f32 "
        "{%0,%1,%2,%3}, {%4,%5,%6,%7}, {%8,%9}, {%0,%1,%2,%3};"
        : "+f"(d[0]), "+f"(d[1]), "+f"(d[2]), "+f"(d[3])
        : "r"(a[0]), "r"(a[1]), "r"(a[2]), "r"(a[3]), "r"(b0), "r"(b1));
}
__device__ __forceinline__ void cp16(uint32_t smem_dst, const void* gsrc) {
    asm volatile("cp.async.cg.shared.global [%0], [%1], 16;" :: "r"(smem_dst), "l"(gsrc));
}
__device__ __forceinline__ void cp_commit() {
    asm volatile("cp.async.commit_group;" ::: "memory");
}
template<int N> __device__ __forceinline__ void cp_wait() {
    asm volatile("cp.async.wait_group %0;" :: "n"(N) : "memory");
}

// ---------------- init ----------------
__global__ void zero_init_kernel() {
    int i = blockIdx.x * blockDim.x + threadIdx.x;
    if (i < NN * RR) d_cnt[i] = 0;
    if (i < GG * HH) d_pool[i] = 0.0f;
    if (i < GG) d_poolcnt[i] = 0.0f;
}

// ---------------- one-time x -> fp16 ----------------
__global__ void xsplit_kernel(const float* __restrict__ x) {
    int i = blockIdx.x * blockDim.x + threadIdx.x;
    if (i >= NN * HH / 2) return;
    float2 v = *(const float2*)(x + i * 2);
    *(__half2*)(d_x16 + (size_t)i * 2) = __float22half2_rn(v);
}

// ---------------- weight prep: transpose -> fp16 ----------------
__global__ void wprep_kernel(const float* __restrict__ bases,
                             const float* __restrict__ root, int layer) {
    int i = blockIdx.x * blockDim.x + threadIdx.x;
    if (i >= KTOT * NTILE) return;
    int k = i >> 7, n = i & 127;
    float w = (k < 512) ? bases[k * 128 + n] : root[(k - 512) * 128 + n];
    d_wt16[(size_t)layer * NTILE * KTOT + (size_t)n * KTOT + k] = __float2half_rn(w);
}

// ---------------- CSR build ----------------
__global__ void count_kernel(const int* __restrict__ ei, const int* __restrict__ et) {
    int e = blockIdx.x * blockDim.x + threadIdx.x;
    if (e >= EE) return;
    int dst = __ldg(ei + EE + e);
    int t   = __ldg(et + e);
    atomicAdd(&d_cnt[dst * RR + t], 1);
}

__global__ void deg_kernel(const int* __restrict__ batch) {
    int n = blockIdx.x * blockDim.x + threadIdx.x;
    if (n >= NN) return;
    const int4* c4 = (const int4*)(d_cnt + n * RR);
    int deg = 0;
    float4* iv = (float4*)(d_invcnt + n * RR);
    #pragma unroll
    for (int q = 0; q < 4; q++) {
        int4 c = c4[q];
        deg += c.x + c.y + c.z + c.w;
        float4 f;
        f.x = 1.0f / (float)(c.x > 1 ? c.x : 1);
        f.y = 1.0f / (float)(c.y > 1 ? c.y : 1);
        f.z = 1.0f / (float)(c.z > 1 ? c.z : 1);
        f.w = 1.0f / (float)(c.w > 1 ? c.w : 1);
        iv[q] = f;
    }
    d_deg[n] = deg;
    atomicAdd(&d_poolcnt[__ldg(batch + n)], 1.0f);
}

// ---------------- hierarchical scan of d_deg -> d_rowptr ----------------
__global__ void partial_kernel() {
    __shared__ int sh[SCAN_B];
    int tid = threadIdx.x;
    int i = blockIdx.x * SCAN_B + tid;
    sh[tid] = (i < NN) ? d_deg[i] : 0;
    __syncthreads();
    for (int off = SCAN_B / 2; off > 0; off >>= 1) {
        if (tid < off) sh[tid] += sh[tid + off];
        __syncthreads();
    }
    if (tid == 0) d_part[blockIdx.x] = sh[0];
}

__global__ void scanpart_kernel() {   // 1 block, 256 threads
    __shared__ int sh[256];
    int tid = threadIdx.x;
    int v = (tid < SCAN_G) ? d_part[tid] : 0;
    sh[tid] = v;
    __syncthreads();
    for (int off = 1; off < 256; off <<= 1) {
        int t = (tid >= off) ? sh[tid - off] : 0;
        __syncthreads();
        sh[tid] += t;
        __syncthreads();
    }
    if (tid < SCAN_G) d_partpre[tid] = sh[tid] - v;   // exclusive
}

__global__ void rowptr_kernel() {
    __shared__ int sh[SCAN_B];
    int tid = threadIdx.x;
    int i = blockIdx.x * SCAN_B + tid;
    int v = (i < NN) ? d_deg[i] : 0;
    sh[tid] = v;
    __syncthreads();
    for (int off = 1; off < SCAN_B; off <<= 1) {
        int t = (tid >= off) ? sh[tid - off] : 0;
        __syncthreads();
        sh[tid] += t;
        __syncthreads();
    }
    if (i < NN) d_rowptr[i] = sh[tid] - v + d_partpre[blockIdx.x];
    if (i == 0) d_rowptr[NN] = EE;
}

__global__ void typeoff_kernel() {
    int n = blockIdx.x * blockDim.x + threadIdx.x;
    if (n >= NN) return;
    int off = d_rowptr[n];
    #pragma unroll
    for (int t = 0; t < RR; t++) {
        d_typeoff[n * RR + t] = off;
        off += d_cnt[n * RR + t];
    }
}

__global__ void scatter_kernel(const int* __restrict__ ei, const int* __restrict__ et) {
    int e = blockIdx.x * blockDim.x + threadIdx.x;
    if (e >= EE) return;
    int src = __ldg(ei + e);
    int dst = __ldg(ei + EE + e);
    int t   = __ldg(et + e);
    int pos = atomicAdd(&d_typeoff[dst * RR + t], 1);
    d_csr[pos] = (unsigned)src | ((unsigned)t << 20);
}

// ---------------- per-layer aggregation (branch-free, MLP-8) -> z16 -----------
__global__ void agg_kernel(const __half* __restrict__ X16,
                           const float* __restrict__ comp /*[R,NB]*/) {
    __shared__ float4 s_comp4[RR];
    int tid = threadIdx.x;
    if (tid < RR) s_comp4[tid] = *(const float4*)(comp + tid * NB);
    __syncthreads();

    int warp = (blockIdx.x * blockDim.x + tid) >> 5;
    int lane = tid & 31;
    if (warp >= NN) return;

    int beg = d_rowptr[warp];
    int end = d_rowptr[warp + 1];
    float inv_t = (lane < RR) ? d_invcnt[warp * RR + lane] : 0.0f;

    float4 acc[NB];
    #pragma unroll
    for (int b = 0; b < NB; b++) acc[b] = make_float4(0.f, 0.f, 0.f, 0.f);

    const __half* Xl = X16 + lane * 4;

    int i = beg;
    for (; i + 32 <= end; i += 32) {
        unsigned pv = d_csr[i + lane];
        #pragma unroll 8
        for (int j = 0; j < 32; j++) {
            unsigned p = __shfl_sync(0xffffffffu, pv, j);
            int src = (int)(p & 0xFFFFFu);
            int t   = (int)(p >> 20);
            float ic = __shfl_sync(0xffffffffu, inv_t, t);
            uint2 raw = *(const uint2*)(Xl + (size_t)src * HH);
            float2 f0 = __half22float2(*(__half2*)&raw.x);
            float2 f1 = __half22float2(*(__half2*)&raw.y);
            float4 cw = s_comp4[t];
            acc[0].x += cw.x * ic * f0.x; acc[0].y += cw.x * ic * f0.y;
            acc[0].z += cw.x * ic * f1.x; acc[0].w += cw.x * ic * f1.y;
            acc[1].x += cw.y * ic * f0.x; acc[1].y += cw.y * ic * f0.y;
            acc[1].z += cw.y * ic * f1.x; acc[1].w += cw.y * ic * f1.y;
            acc[2].x += cw.z * ic * f0.x; acc[2].y += cw.z * ic * f0.y;
            acc[2].z += cw.z * ic * f1.x; acc[2].w += cw.z * ic * f1.y;
            acc[3].x += cw.w * ic * f0.x; acc[3].y += cw.w * ic * f0.y;
            acc[3].z += cw.w * ic * f1.x; acc[3].w += cw.w * ic * f1.y;
        }
    }
    for (; i < end; i++) {
        unsigned p = d_csr[i];
        int src = (int)(p & 0xFFFFFu);
        int t   = (int)(p >> 20);
        float ic = __shfl_sync(0xffffffffu, inv_t, t);
        uint2 raw = *(const uint2*)(Xl + (size_t)src * HH);
        float2 f0 = __half22float2(*(__half2*)&raw.x);
        float2 f1 = __half22float2(*(__half2*)&raw.y);
        float4 cw = s_comp4[t];
        acc[0].x += cw.x * ic * f0.x; acc[0].y += cw.x * ic * f0.y;
        acc[0].z += cw.x * ic * f1.x; acc[0].w += cw.x * ic * f1.y;
        acc[1].x += cw.y * ic * f0.x; acc[1].y += cw.y * ic * f0.y;
        acc[1].z += cw.y * ic * f1.x; acc[1].w += cw.y * ic * f1.y;
        acc[2].x += cw.z * ic * f0.x; acc[2].y += cw.z * ic * f0.y;
        acc[2].z += cw.z * ic * f1.x; acc[2].w += cw.z * ic * f1.y;
        acc[3].x += cw.w * ic * f0.x; acc[3].y += cw.w * ic * f0.y;
        acc[3].z += cw.w * ic * f1.x; acc[3].w += cw.w * ic * f1.y;
    }

    size_t base = (size_t)warp * 512 + lane * 4;
    #pragma unroll
    for (int b = 0; b < NB; b++) {
        __half2 h0 = __float22half2_rn(make_float2(acc[b].x, acc[b].y));
        __half2 h1 = __float22half2_rn(make_float2(acc[b].z, acc[b].w));
        uint2 v;
        v.x = *(uint32_t*)&h0;
        v.y = *(uint32_t*)&h1;
        *(uint2*)(d_z16 + base + b * 128) = v;
    }
}

// ---------------- tensor-core GEMM: fp16 single-term HMMA, 2 CTAs/SM ----------
// stage: A[16K] B[16K]; tiles [128 rows][64 k] fp16, row stride 128B, SW128.
__global__ void __launch_bounds__(256, 2)
tc_gemm_kernel(const __half* __restrict__ Xin,
               __half* __restrict__ OUT16,              // fp16 (layers 1,2)
               const float* __restrict__ bias, int relu, int layer,
               int do_pool, const int* __restrict__ batch) {
    extern __shared__ __align__(1024) char smem[];
    uint32_t sb = smem_u32(smem);
    int tid = threadIdx.x;
    int wid = tid >> 5;
    int lane = tid & 31;
    int row0 = blockIdx.x * MTILE;

    const __half* W16 = d_wt16 + (size_t)layer * NTILE * KTOT;

    int lr[4], lc[4];
    uint32_t ldst[4];
    #pragma unroll
    for (int i = 0; i < 4; i++) {
        int g = tid + i * 256;
        lr[i] = g >> 3;
        lc[i] = (g & 7) * 8;
        ldst[i] = SW128((uint32_t)(lr[i] * 128 + lc[i] * 2));
    }

    #define LOAD_CHUNK(c, stage)                                                      \
    {                                                                                 \
        uint32_t s0 = sb + (stage) * STAGE_BYTES;                                     \
        _Pragma("unroll")                                                             \
        for (int i = 0; i < 4; i++) {                                                 \
            int gm = row0 + lr[i];                                                    \
            const __half* a = ((c) < 8)                                               \
                ? (d_z16 + (size_t)gm * 512 + (c) * KCHUNK + lc[i])                   \
                : (Xin + (size_t)gm * 128 + ((c) - 8) * KCHUNK + lc[i]);              \
            cp16(s0 + ldst[i], a);                                                    \
            const __half* b = W16 + (size_t)lr[i] * KTOT + (c) * KCHUNK + lc[i];      \
            cp16(s0 + B_OFF + ldst[i], b);                                            \
        }                                                                             \
    }

    int wm = (wid & 1) * 64;
    int wn = (wid >> 1) * 32;

    int sub = lane & 7, g = lane >> 3;
    int a_r = sub + ((g & 1) << 3);
    int a_k = (g >> 1) << 3;
    int b_r = sub + ((g >> 1) << 3);
    int b_k = (g & 1) << 3;

    float acc[4][4][4];
    #pragma unroll
    for (int mt = 0; mt < 4; mt++)
        #pragma unroll
        for (int nt = 0; nt < 4; nt++)
            #pragma unroll
            for (int q = 0; q < 4; q++) acc[mt][nt][q] = 0.0f;

    LOAD_CHUNK(0, 0);
    cp_commit();

    for (int c = 0; c < NCHUNKS; c++) {
        if (c + 1 < NCHUNKS) {
            LOAD_CHUNK(c + 1, (c + 1) & 1);
            cp_commit();
            cp_wait<1>();
        } else {
            cp_wait<0>();
        }
        __syncthreads();

        uint32_t s0 = sb + (c & 1) * STAGE_BYTES;
        #pragma unroll
        for (int ks = 0; ks < 4; ks++) {
            uint32_t ah[4][4], bh[2][4];
            #pragma unroll
            for (int mt = 0; mt < 4; mt++) {
                uint32_t off = SW128((uint32_t)((wm + mt * 16 + a_r) * 128 + (ks * 16 + a_k) * 2));
                ldsm_x4(ah[mt], s0 + off);
            }
            #pragma unroll
            for (int nt2 = 0; nt2 < 2; nt2++) {
                uint32_t off = SW128((uint32_t)((wn + nt2 * 16 + b_r) * 128 + (ks * 16 + b_k) * 2));
                ldsm_x4(bh[nt2], s0 + B_OFF + off);
            }
            #pragma unroll
            for (int mt = 0; mt < 4; mt++)
                #pragma unroll
                for (int nt = 0; nt < 4; nt++) {
                    uint32_t b0 = bh[nt >> 1][(nt & 1) * 2], b1 = bh[nt >> 1][(nt & 1) * 2 + 1];
                    mma_f16(acc[mt][nt], ah[mt], b0, b1);
                }
        }
        __syncthreads();
    }
    #undef LOAD_CHUNK

    if (!do_pool) {
        #pragma unroll
        for (int mt = 0; mt < 4; mt++) {
            int rr2[2];
            rr2[0] = row0 + wm + mt * 16 + (lane >> 2);
            rr2[1] = rr2[0] + 8;
            #pragma unroll
            for (int nt = 0; nt < 4; nt++) {
                int col = wn + nt * 8 + ((lane & 3) << 1);
                float2 b2 = *(const float2*)(bias + col);
                #pragma unroll
                for (int h2i = 0; h2i < 2; h2i++) {
                    int r = rr2[h2i];
                    if (r >= NN) continue;
                    float2 v;
                    v.x = acc[mt][nt][h2i * 2 + 0] + b2.x;
                    v.y = acc[mt][nt][h2i * 2 + 1] + b2.y;
                    if (relu) { v.x = fmaxf(v.x, 0.f); v.y = fmaxf(v.y, 0.f); }
                    *(__half2*)(OUT16 + (size_t)r * 128 + col) = __float22half2_rn(v);
                }
            }
        }
    } else {
        float pacc[8];
        int curg = -1;
        int colb = wn + ((lane & 3) << 1);
        #pragma unroll
        for (int mt = 0; mt < 4; mt++) {
            #pragma unroll
            for (int h2i = 0; h2i < 2; h2i++) {
                int r = row0 + wm + mt * 16 + (lane >> 2) + h2i * 8;
                if (r >= NN) continue;
                int gph = __ldg(batch + r);
                if (gph != curg) {
                    if (curg >= 0) {
                        #pragma unroll
                        for (int j = 0; j < 4; j++) {
                            atomicAdd(&d_pool[curg * 128 + colb + j * 8], pacc[j * 2]);
                            atomicAdd(&d_pool[curg * 128 + colb + j * 8 + 1], pacc[j * 2 + 1]);
                        }
                    }
                    curg = gph;
                    #pragma unroll
                    for (int j = 0; j < 8; j++) pacc[j] = 0.f;
                }
                #pragma unroll
                for (int nt = 0; nt < 4; nt++) {
                    float2 b2 = *(const float2*)(bias + colb + nt * 8);
                    pacc[nt * 2 + 0] += acc[mt][nt][h2i * 2 + 0] + b2.x;
                    pacc[nt * 2 + 1] += acc[mt][nt][h2i * 2 + 1] + b2.y;
                }
            }
        }
        if (curg >= 0) {
            #pragma unroll
            for (int j = 0; j < 4; j++) {
                atomicAdd(&d_pool[curg * 128 + colb + j * 8], pacc[j * 2]);
                atomicAdd(&d_pool[curg * 128 + colb + j * 8 + 1], pacc[j * 2 + 1]);
            }
        }
    }
}

// ---------------- final ----------------
__global__ void final_kernel(const int* __restrict__ rl,
                             const float* __restrict__ rel_emb,
                             const float* __restrict__ lw,   // [256,2]
                             const float* __restrict__ lb,   // [2]
                             float* __restrict__ out) {
    int t = threadIdx.x;
    if (t >= GG * NC) return;
    int g = t >> 1, c = t & 1;
    float cnt = d_poolcnt[g];
    float invc = 1.0f / (cnt > 1.0f ? cnt : 1.0f);
    const float* re = rel_emb + (size_t)rl[g] * 128;
    float s = 0.f;
    for (int j = 0; j < 128; j++) s += d_pool[g * 128 + j] * invc * lw[j * 2 + c];
    for (int j = 0; j < 128; j++) s += re[j] * lw[(128 + j) * 2 + c];
    out[g * 2 + c] = s + lb[c];
}

// ---------------- launch ----------------
extern "C" void kernel_launch(void* const* d_in, const int* in_sizes, int n_in,
                              void* d_out, int out_size) {
    const float* x      = (const float*)d_in[0];
    const int*   ei     = (const int*)d_in[1];
    const int*   et     = (const int*)d_in[2];
    const int*   batch  = (const int*)d_in[3];
    const int*   rl     = (const int*)d_in[4];
    const float* relemb = (const float*)d_in[6];
    const float* bases[3] = {(const float*)d_in[7],  (const float*)d_in[11], (const float*)d_in[15]};
    const float* comp[3]  = {(const float*)d_in[8],  (const float*)d_in[12], (const float*)d_in[16]};
    const float* root[3]  = {(const float*)d_in[9],  (const float*)d_in[13], (const float*)d_in[17]};
    const float* bias[3]  = {(const float*)d_in[10], (const float*)d_in[14], (const float*)d_in[18]};
    const float* lin_w  = (const float*)d_in[19];
    const float* lin_b  = (const float*)d_in[20];
    float* out = (float*)d_out;

    cudaFuncSetAttribute(tc_gemm_kernel, cudaFuncAttributeMaxDynamicSharedMemorySize, GEMM_SMEM);

    void *p_x16, *p_h116, *p_h216;
    cudaGetSymbolAddress(&p_x16, d_x16);
    cudaGetSymbolAddress(&p_h116, d_h1_16);
    cudaGetSymbolAddress(&p_h216, d_h2_16);

    const int TB = 256;
    zero_init_kernel<<<(NN * RR + TB - 1) / TB, TB>>>();
    count_kernel<<<(EE + TB - 1) / TB, TB>>>(ei, et);
    deg_kernel<<<(NN + TB - 1) / TB, TB>>>(batch);
    partial_kernel<<<SCAN_G, SCAN_B>>>();
    scanpart_kernel<<<1, 256>>>();
    rowptr_kernel<<<SCAN_G, SCAN_B>>>();
    typeoff_kernel<<<(NN + TB - 1) / TB, TB>>>();
    scatter_kernel<<<(EE + TB - 1) / TB, TB>>>(ei, et);
    xsplit_kernel<<<(NN * HH / 2 + TB - 1) / TB, TB>>>(x);

    int wpBlocks = (KTOT * NTILE + TB - 1) / TB;
    wprep_kernel<<<wpBlocks, TB>>>(bases[0], root[0], 0);
    wprep_kernel<<<wpBlocks, TB>>>(bases[1], root[1], 1);
    wprep_kernel<<<wpBlocks, TB>>>(bases[2], root[2], 2);

    int aggBlocks = (NN * 32 + TB - 1) / TB;

    // layer 1: agg(x16) -> z16; gemm -> h1_16, relu
    agg_kernel<<<aggBlocks, TB>>>((const __half*)p_x16, comp[0]);
    tc_gemm_kernel<<<GEMM_GRID, 256, GEMM_SMEM>>>(
        (const __half*)p_x16, (__half*)p_h116, bias[0], 1, 0, 0, batch);
    // layer 2: agg(h1_16) -> z16; gemm -> h2_16, relu
    agg_kernel<<<aggBlocks, TB>>>((const __half*)p_h116, comp[1]);
    tc_gemm_kernel<<<GEMM_GRID, 256, GEMM_SMEM>>>(
        (const __half*)p_h116, (__half*)p_h216, bias[1], 1, 1, 0, batch);
    // layer 3: agg(h2_16) -> z16; gemm pools directly, no relu
    agg_kernel<<<aggBlocks, TB>>>((const __half*)p_h216, comp[2]);
    tc_gemm_kernel<<<GEMM_GRID, 256, GEMM_SMEM>>>(
        (const __half*)p_h216, (__half*)nullptr, bias[2], 0, 2, 1, batch);

    final_kernel<<<1, 128>>>(rl, relemb, lin_w, lin_b, out);
}